// round 2
// baseline (speedup 1.0000x reference)
#include <cuda_runtime.h>

#define B_  512
#define T_  2048
#define I_  33
#define H_  64
#define O_  2
#define BT_ (B_ * T_)

// Packed fp32x2 FMA (Blackwell FFMA2) — only reachable via PTX fma.rn.f32x2.
__device__ __forceinline__ void ffma2(float2& d, float2 a, float2 b) {
    asm("fma.rn.f32x2 %0, %1, %2, %0;"
        : "+l"(*reinterpret_cast<unsigned long long*>(&d))
        : "l"(*reinterpret_cast<const unsigned long long*>(&a)),
          "l"(*reinterpret_cast<const unsigned long long*>(&b)));
}

__device__ __forceinline__ float fast_tanh(float x) {
    float ax = fabsf(x);
    float e  = __expf(-2.0f * ax);
    float r  = __fdividef(1.0f - e, 1.0f + e);
    return copysignf(r, x);
}

// ---------------- Phase 1: xW = x @ W_ih^T + b_ih  (written into hidden region) ----------------
__global__ __launch_bounds__(128) void xw_kernel(
    const float* __restrict__ x, const float* __restrict__ W_ih,
    const float* __restrict__ b_ih, float* __restrict__ xw)
{
    __shared__ float Wc[I_ * H_];              // col-major: Wc[i*64 + j] = W_ih[j][i]
    __shared__ float bsh[H_];
    __shared__ __align__(16) float xs[128 * I_];

    int tid = threadIdx.x;
    for (int e = tid; e < I_ * H_; e += 128) {
        int i = e >> 6, j = e & 63;
        Wc[e] = W_ih[j * I_ + i];
    }
    if (tid < H_) bsh[tid] = b_ih[tid];

    // Cooperative, coalesced x staging: 128 rows * 33 floats = 1056 float4, contiguous + 16B aligned.
    const float4* xg = (const float4*)(x + (size_t)blockIdx.x * 128 * I_);
    float4* xs4 = (float4*)xs;
    #pragma unroll
    for (int q = 0; q < 9; ++q) {
        int idx = tid + q * 128;
        if (idx < (128 * I_) / 4) xs4[idx] = xg[idx];
    }
    __syncthreads();

    float2 acc[32];
    const float2* b2 = (const float2*)bsh;
    #pragma unroll
    for (int q = 0; q < 32; ++q) acc[q] = b2[q];

    const float* xr = xs + tid * I_;           // stride 33 floats -> conflict-free (33 ≡ 1 mod 32)
    #pragma unroll 1
    for (int i = 0; i < I_; ++i) {
        float xi = xr[i];
        float2 xi2 = make_float2(xi, xi);
        const float4* wr = (const float4*)(Wc + i * H_);   // lane-uniform -> smem broadcast
        #pragma unroll
        for (int q = 0; q < 16; ++q) {
            float4 w = wr[q];
            ffma2(acc[2 * q],     make_float2(w.x, w.y), xi2);
            ffma2(acc[2 * q + 1], make_float2(w.z, w.w), xi2);
        }
    }

    size_t r = (size_t)blockIdx.x * 128 + tid;
    float4* op = (float4*)(xw + r * H_);
    #pragma unroll
    for (int q = 0; q < 16; ++q)
        op[q] = make_float4(acc[2 * q].x, acc[2 * q].y, acc[2 * q + 1].x, acc[2 * q + 1].y);
}

// ---------------- Phase 2: sequential recurrence, in-place xW -> h ----------------
__device__ __forceinline__ void rnn_step(
    const float* __restrict__ hr, const float2* wA, const float2* wB,
    float bA, float bB, float xA, float xB,
    float* __restrict__ cb, float* __restrict__ hrow, int l)
{
    float2 aA = make_float2(0.f, 0.f), aB = make_float2(0.f, 0.f);
    #pragma unroll
    for (int q = 0; q < 16; ++q) {
        float4 h4 = ((const float4*)hr)[q];                // lane-uniform broadcast LDS.128
        float2 p0 = make_float2(h4.x, h4.y);
        float2 p1 = make_float2(h4.z, h4.w);
        ffma2(aA, wA[2 * q],     p0);
        ffma2(aB, wB[2 * q],     p0);
        ffma2(aA, wA[2 * q + 1], p1);
        ffma2(aB, wB[2 * q + 1], p1);
    }
    float hA = fast_tanh((aA.x + aA.y) + (xA + bA));
    float hB = fast_tanh((aB.x + aB.y) + (xB + bB));
    cb[l]      = hA;  cb[l + 32]   = hB;                   // overwrite xW slot with h (output)
    hrow[l]    = hA;  hrow[l + 32] = hB;                   // smem for next step's broadcast
}

__global__ __launch_bounds__(128, 1) void rnn_kernel(
    float* __restrict__ hs, const float* __restrict__ h0,
    const float* __restrict__ W_hh, const float* __restrict__ b_hh)
{
    __shared__ __align__(16) float hb[4][H_];
    int w = threadIdx.x >> 5;
    int l = threadIdx.x & 31;
    int row = blockIdx.x * 4 + w;

    // W_hh rows l and l+32 fully register-resident as k-pairs (128 regs).
    float2 wA[32], wB[32];
    const float4* wra = (const float4*)(W_hh + l * H_);
    const float4* wrb = (const float4*)(W_hh + (l + 32) * H_);
    #pragma unroll
    for (int q = 0; q < 16; ++q) {
        float4 a = wra[q];
        wA[2 * q] = make_float2(a.x, a.y); wA[2 * q + 1] = make_float2(a.z, a.w);
        float4 b = wrb[q];
        wB[2 * q] = make_float2(b.x, b.y); wB[2 * q + 1] = make_float2(b.z, b.w);
    }
    float bA = b_hh[l], bB = b_hh[l + 32];

    hb[w][l]      = h0[row * H_ + l];
    hb[w][l + 32] = h0[row * H_ + l + 32];
    __syncwarp();

    float* base = hs + (size_t)row * T_ * H_;
    // prefetch depth 2 against DRAM latency on streaming xW reads
    float xA0 = base[l],       xB0 = base[l + 32];
    float xA1 = base[H_ + l],  xB1 = base[H_ + l + 32];
    float* hrow = hb[w];

    for (int t = 0; t < T_; t += 2) {
        rnn_step(hrow, wA, wB, bA, bB, xA0, xB0, base + (size_t)t * H_, hrow, l);
        {
            int tn = (t + 2 < T_) ? t + 2 : T_ - 1;
            const float* nb = base + (size_t)tn * H_;
            xA0 = nb[l]; xB0 = nb[l + 32];
        }
        __syncwarp();
        rnn_step(hrow, wA, wB, bA, bB, xA1, xB1, base + (size_t)(t + 1) * H_, hrow, l);
        {
            int tn = (t + 3 < T_) ? t + 3 : T_ - 1;
            const float* nb = base + (size_t)tn * H_;
            xA1 = nb[l]; xB1 = nb[l + 32];
        }
        __syncwarp();
    }
}

// ---------------- Phase 3: predictions = hs @ W_ro^T + b_ro ----------------
__global__ __launch_bounds__(256) void pred_kernel(
    const float* __restrict__ hs, const float* __restrict__ W_ro,
    const float* __restrict__ b_ro, float* __restrict__ pred)
{
    __shared__ float w0[H_], w1[H_];
    int tid = threadIdx.x;
    if (tid < H_) { w0[tid] = W_ro[tid]; w1[tid] = W_ro[H_ + tid]; }
    __syncthreads();

    size_t r = (size_t)blockIdx.x * 256 + tid;
    const float4* hp = (const float4*)(hs + r * H_);
    float p0a = 0.f, p0b = 0.f, p1a = 0.f, p1b = 0.f;
    #pragma unroll
    for (int q = 0; q < 16; ++q) {
        float4 h = hp[q];
        p0a += h.x * w0[4 * q]     + h.z * w0[4 * q + 2];
        p0b += h.y * w0[4 * q + 1] + h.w * w0[4 * q + 3];
        p1a += h.x * w1[4 * q]     + h.z * w1[4 * q + 2];
        p1b += h.y * w1[4 * q + 1] + h.w * w1[4 * q + 3];
    }
    ((float2*)pred)[r] = make_float2(p0a + p0b + b_ro[0], p1a + p1b + b_ro[1]);
}

extern "C" void kernel_launch(void* const* d_in, const int* in_sizes, int n_in,
                              void* d_out, int out_size)
{
    const float* x   = (const float*)d_in[0];
    const float* h0  = (const float*)d_in[1];
    const float* Wih = (const float*)d_in[2];
    const float* Whh = (const float*)d_in[3];
    const float* bih = (const float*)d_in[4];
    const float* bhh = (const float*)d_in[5];
    const float* Wro = (const float*)d_in[6];
    const float* bro = (const float*)d_in[7];

    float* out  = (float*)d_out;
    float* pred = out;                               // [B,T,O]
    float* hsb  = out + (size_t)B_ * T_ * O_;        // [B,T,H] — staged as xW, overwritten with h

    xw_kernel  <<<BT_ / 128, 128>>>(x, Wih, bih, hsb);
    rnn_kernel <<<B_ / 4,    128>>>(hsb, h0, Whh, bhh);
    pred_kernel<<<BT_ / 256, 256>>>(hsb, Wro, bro, pred);
}